// round 1
// baseline (speedup 1.0000x reference)
#include <cuda_runtime.h>
#include <cuda_bf16.h>
#include <math.h>
#include <math_constants.h>

#define BB 2
#define SS 2048
#define DD 1024
#define HH 16
#define DK 64

// ---------------- scratch (allocation-free: __device__ globals) ----------------
__device__ float g_qbuf[BB*HH*SS*DK];   // [b*H+h][s][dk]
__device__ float g_kbuf[BB*HH*SS*DK];
__device__ float g_vbuf[BB*HH*SS*DK];
__device__ float g_attn[BB*SS*DD];      // [b][s][h*64+dk]

// ---------------- projection GEMM: C = A @ W^T  (M=4096, N=K=1024) -------------
// mode 0: RoPE + scatter to headed layout; mode 1: scatter headed (V); mode 2: plain (Wo)
#define GBM 128
#define GBN 128
#define GBK 16
#define GPAD 4

__global__ __launch_bounds__(256)
void gemm_kernel(const float* __restrict__ A, const float* __restrict__ W,
                 const int* __restrict__ tp, float* __restrict__ out, int mode)
{
    __shared__ float As[GBK][GBM + GPAD];
    __shared__ float Bs[GBK][GBN + GPAD];

    const int tid = threadIdx.x;
    const int tx = tid & 15;      // 16 col groups of 8
    const int ty = tid >> 4;      // 16 row groups of 8
    const int m0 = blockIdx.y * GBM;
    const int n0 = blockIdx.x * GBN;

    float acc[8][8];
    #pragma unroll
    for (int i = 0; i < 8; i++)
        #pragma unroll
        for (int j = 0; j < 8; j++) acc[i][j] = 0.f;

    for (int k0 = 0; k0 < DD; k0 += GBK) {
        #pragma unroll
        for (int it = 0; it < 2; it++) {
            int idx = tid + it * 256;       // 0..511
            int row = idx >> 2;             // 0..127
            int kq  = (idx & 3) * 4;        // 0,4,8,12
            float4 va = *(const float4*)&A[(size_t)(m0 + row) * DD + k0 + kq];
            As[kq+0][row] = va.x; As[kq+1][row] = va.y;
            As[kq+2][row] = va.z; As[kq+3][row] = va.w;
            float4 vb = *(const float4*)&W[(size_t)(n0 + row) * DD + k0 + kq];
            Bs[kq+0][row] = vb.x; Bs[kq+1][row] = vb.y;
            Bs[kq+2][row] = vb.z; Bs[kq+3][row] = vb.w;
        }
        __syncthreads();
        #pragma unroll
        for (int k = 0; k < GBK; k++) {
            float4 a0 = *(const float4*)&As[k][ty*8];
            float4 a1 = *(const float4*)&As[k][ty*8+4];
            float4 b0 = *(const float4*)&Bs[k][tx*8];
            float4 b1 = *(const float4*)&Bs[k][tx*8+4];
            float ar[8] = {a0.x,a0.y,a0.z,a0.w,a1.x,a1.y,a1.z,a1.w};
            float br[8] = {b0.x,b0.y,b0.z,b0.w,b1.x,b1.y,b1.z,b1.w};
            #pragma unroll
            for (int i = 0; i < 8; i++)
                #pragma unroll
                for (int j = 0; j < 8; j++)
                    acc[i][j] += ar[i] * br[j];
        }
        __syncthreads();
    }

    const int ncol = n0 + tx * 8;
    if (mode == 2) {
        #pragma unroll
        for (int i = 0; i < 8; i++) {
            int m = m0 + ty * 8 + i;
            float* dst = out + (size_t)m * DD + ncol;
            *(float4*)dst       = make_float4(acc[i][0], acc[i][1], acc[i][2], acc[i][3]);
            *(float4*)(dst + 4) = make_float4(acc[i][4], acc[i][5], acc[i][6], acc[i][7]);
        }
    } else {
        const int h   = ncol >> 6;
        const int dk0 = ncol & 63;
        float inv[4];
        if (mode == 0) {
            #pragma unroll
            for (int q = 0; q < 4; q++)
                inv[q] = powf(10000.0f, -(float)(dk0 + 2*q) * (1.0f / 64.0f));
        }
        #pragma unroll
        for (int i = 0; i < 8; i++) {
            int m = m0 + ty * 8 + i;
            int bb = m >> 11;
            int s  = m & (SS - 1);
            float* dst = out + ((size_t)(bb * HH + h) * SS + s) * DK + dk0;
            float r[8];
            if (mode == 0) {
                float fp = (float)tp[m];
                #pragma unroll
                for (int q = 0; q < 4; q++) {
                    float sn, cs;
                    sincosf(fp * inv[q], &sn, &cs);
                    float xe = acc[i][2*q], xo = acc[i][2*q+1];
                    r[2*q]   = cs * xe - sn * xo;
                    r[2*q+1] = sn * xe + cs * xo;
                }
            } else {
                #pragma unroll
                for (int q = 0; q < 8; q++) r[q] = acc[i][q];
            }
            *(float4*)dst       = make_float4(r[0], r[1], r[2], r[3]);
            *(float4*)(dst + 4) = make_float4(r[4], r[5], r[6], r[7]);
        }
    }
}

// ---------------- flash attention (causal), fp32 -------------------------------
// Block: 64 query rows x DK=64, loops over 64-key tiles. 256 threads, 4x4 micro.
#define AST 68           // smem row stride (floats), 16B-aligned
#define ASM_BYTES (4 * 64 * AST * 4)

__global__ __launch_bounds__(256)
void attn_kernel(const float* __restrict__ qb, const float* __restrict__ kb,
                 const float* __restrict__ vb, float* __restrict__ aout)
{
    extern __shared__ float sm[];
    float* Qt = sm;                 // Qt[d*AST + r]  (transposed)
    float* Kt = sm + 64 * AST;      // Kt[d*AST + c]  (transposed)
    float* Vs = sm + 2 * 64 * AST;  // Vs[c*AST + d]  (natural)
    float* Pt = sm + 3 * 64 * AST;  // Pt[c*AST + r]  (transposed P)

    const int tid = threadIdx.x;
    const int rg = tid >> 4;        // 16 row groups (4 rows each)
    const int cg = tid & 15;        // 16 col groups (4 cols each)
    const int qt = gridDim.x - 1 - blockIdx.x;   // heavy tiles first
    const int bh = blockIdx.y;
    const int q0 = qt * 64;

    const float* qh = qb + (size_t)bh * SS * DK;
    const float* kh = kb + (size_t)bh * SS * DK;
    const float* vh = vb + (size_t)bh * SS * DK;

    // load Q tile transposed
    #pragma unroll
    for (int it = 0; it < 4; it++) {
        int idx = tid + it * 256;     // 0..1023
        int dq = idx >> 6;            // 0..15
        int r  = idx & 63;
        float4 v = *(const float4*)&qh[(size_t)(q0 + r) * DK + dq * 4];
        Qt[(dq*4+0)*AST + r] = v.x;
        Qt[(dq*4+1)*AST + r] = v.y;
        Qt[(dq*4+2)*AST + r] = v.z;
        Qt[(dq*4+3)*AST + r] = v.w;
    }

    float m_r[4], l_r[4], o[4][4];
    #pragma unroll
    for (int i = 0; i < 4; i++) {
        m_r[i] = -CUDART_INF_F; l_r[i] = 0.f;
        #pragma unroll
        for (int j = 0; j < 4; j++) o[i][j] = 0.f;
    }
    __syncthreads();

    for (int kt = 0; kt <= qt; kt++) {
        const int k0 = kt * 64;
        // load K (transposed) and V (natural)
        #pragma unroll
        for (int it = 0; it < 4; it++) {
            int idx = tid + it * 256;
            int dq = idx >> 6;
            int r  = idx & 63;
            float4 v = *(const float4*)&kh[(size_t)(k0 + r) * DK + dq * 4];
            Kt[(dq*4+0)*AST + r] = v.x;
            Kt[(dq*4+1)*AST + r] = v.y;
            Kt[(dq*4+2)*AST + r] = v.z;
            Kt[(dq*4+3)*AST + r] = v.w;
            int c  = idx >> 4;        // 0..63
            int dv = idx & 15;
            float4 w = *(const float4*)&vh[(size_t)(k0 + c) * DK + dv * 4];
            *(float4*)&Vs[c*AST + dv*4] = w;
        }
        __syncthreads();

        // S = Q K^T tile (4x4 per thread)
        float s[4][4];
        #pragma unroll
        for (int i = 0; i < 4; i++)
            #pragma unroll
            for (int j = 0; j < 4; j++) s[i][j] = 0.f;
        #pragma unroll 8
        for (int d = 0; d < 64; d++) {
            float4 q4 = *(const float4*)&Qt[d*AST + rg*4];
            float4 k4 = *(const float4*)&Kt[d*AST + cg*4];
            float qa[4] = {q4.x, q4.y, q4.z, q4.w};
            float ka[4] = {k4.x, k4.y, k4.z, k4.w};
            #pragma unroll
            for (int i = 0; i < 4; i++)
                #pragma unroll
                for (int j = 0; j < 4; j++)
                    s[i][j] += qa[i] * ka[j];
        }

        const bool diag = (kt == qt);
        float p[4][4];
        #pragma unroll
        for (int i = 0; i < 4; i++) {
            float rm = -CUDART_INF_F;
            #pragma unroll
            for (int j = 0; j < 4; j++) {
                float v = s[i][j] * 0.125f;
                if (diag && (cg*4 + j > rg*4 + i)) v = -CUDART_INF_F;
                s[i][j] = v;
                rm = fmaxf(rm, v);
            }
            #pragma unroll
            for (int off = 1; off < 16; off <<= 1)
                rm = fmaxf(rm, __shfl_xor_sync(0xffffffffu, rm, off));
            float mn = fmaxf(m_r[i], rm);
            float a  = __expf(m_r[i] - mn);
            float ps = 0.f;
            #pragma unroll
            for (int j = 0; j < 4; j++) {
                p[i][j] = __expf(s[i][j] - mn);
                ps += p[i][j];
            }
            #pragma unroll
            for (int off = 1; off < 16; off <<= 1)
                ps += __shfl_xor_sync(0xffffffffu, ps, off);
            l_r[i] = l_r[i] * a + ps;
            m_r[i] = mn;
            #pragma unroll
            for (int j = 0; j < 4; j++) o[i][j] *= a;
        }

        // write P transposed
        #pragma unroll
        for (int j = 0; j < 4; j++)
            *(float4*)&Pt[(cg*4+j)*AST + rg*4] =
                make_float4(p[0][j], p[1][j], p[2][j], p[3][j]);
        __syncthreads();

        // O += P @ V
        #pragma unroll 8
        for (int k = 0; k < 64; k++) {
            float4 p4 = *(const float4*)&Pt[k*AST + rg*4];
            float4 v4 = *(const float4*)&Vs[k*AST + cg*4];
            float pa[4] = {p4.x, p4.y, p4.z, p4.w};
            float va[4] = {v4.x, v4.y, v4.z, v4.w};
            #pragma unroll
            for (int i = 0; i < 4; i++)
                #pragma unroll
                for (int j = 0; j < 4; j++)
                    o[i][j] += pa[i] * va[j];
        }
        __syncthreads();
    }

    const int b = bh >> 4, h = bh & 15;
    #pragma unroll
    for (int i = 0; i < 4; i++) {
        float invl = 1.0f / l_r[i];
        int srow = q0 + rg*4 + i;
        float* dst = aout + ((size_t)(b * SS + srow)) * DD + h * DK + cg * 4;
        *(float4*)dst = make_float4(o[i][0]*invl, o[i][1]*invl,
                                    o[i][2]*invl, o[i][3]*invl);
    }
}

// ---------------- launch --------------------------------------------------------
extern "C" void kernel_launch(void* const* d_in, const int* in_sizes, int n_in,
                              void* d_out, int out_size)
{
    (void)in_sizes; (void)n_in; (void)out_size;
    const float* x  = (const float*)d_in[0];
    const float* Wq = (const float*)d_in[1];
    const float* Wk = (const float*)d_in[2];
    const float* Wv = (const float*)d_in[3];
    const float* Wo = (const float*)d_in[4];
    const int*   tp = (const int*)d_in[5];
    float* out = (float*)d_out;

    float *qb, *kb, *vb, *ab;
    cudaGetSymbolAddress((void**)&qb, g_qbuf);
    cudaGetSymbolAddress((void**)&kb, g_kbuf);
    cudaGetSymbolAddress((void**)&vb, g_vbuf);
    cudaGetSymbolAddress((void**)&ab, g_attn);

    dim3 blk(256);
    dim3 gproj(DD / GBN, (BB * SS) / GBM);   // (8, 32)

    gemm_kernel<<<gproj, blk>>>(x, Wq, tp, qb, 0);
    gemm_kernel<<<gproj, blk>>>(x, Wk, tp, kb, 0);
    gemm_kernel<<<gproj, blk>>>(x, Wv, tp, vb, 1);

    cudaFuncSetAttribute(attn_kernel, cudaFuncAttributeMaxDynamicSharedMemorySize, ASM_BYTES);
    attn_kernel<<<dim3(SS / 64, BB * HH), blk, ASM_BYTES>>>(qb, kb, vb, ab);

    gemm_kernel<<<gproj, blk>>>(ab, Wo, tp, out, 2);
}

// round 3
// speedup vs baseline: 1.2460x; 1.2460x over previous
#include <cuda_runtime.h>
#include <cuda_bf16.h>
#include <math.h>
#include <math_constants.h>
#include <cstdint>

#define BB 2
#define SS 2048
#define DD 1024
#define HH 16
#define DK 64

// ---------------- scratch (allocation-free: __device__ globals) ----------------
__device__ float g_qbuf[BB*HH*SS*DK];   // [b*H+h][s][dk]
__device__ float g_kbuf[BB*HH*SS*DK];
__device__ float g_vbuf[BB*HH*SS*DK];
__device__ float g_attn[BB*SS*DD];      // [b][s][h*64+dk]
__device__ float g_ct[BB*SS*32];        // cos table [m][p]
__device__ float g_st[BB*SS*32];        // sin table [m][p]

// ======================= RoPE table precompute ==================================
__global__ void rope_tab_kernel(const int* __restrict__ tp, float* __restrict__ ct,
                                float* __restrict__ st)
{
    int idx = blockIdx.x * blockDim.x + threadIdx.x;  // m*32 + p
    if (idx >= BB*SS*32) return;
    int m = idx >> 5;
    int p = idx & 31;
    float inv = powf(10000.0f, -(float)(2*p) * (1.0f/64.0f));
    float freq = (float)tp[m] * inv;
    float sn, cs;
    sincosf(freq, &sn, &cs);
    ct[idx] = cs;
    st[idx] = sn;
}

// ======================= mma.sync bf16 hi/lo GEMM ===============================
// C[M=4096, N=1024] = A @ W^T, fp32 in/out, bf16 3-pass (hihi + hilo + lohi).
// Tile 128x128, K-tile 32. 256 threads = 8 warps (2 M x 4 N), warp tile 64x32.
// mode 0: RoPE + head scatter (Q/K); 1: head scatter (V); 2: plain (Wo)
#define KT 32
#define SROW 20   // uint32 stride per row: 20 % 8 == 4 -> conflict-free frag loads

__device__ __forceinline__ uint32_t pack_bf16(float a, float b) {
    __nv_bfloat16 ha = __float2bfloat16_rn(a);
    __nv_bfloat16 hb = __float2bfloat16_rn(b);
    return (uint32_t)__bfloat16_as_ushort(ha) | ((uint32_t)__bfloat16_as_ushort(hb) << 16);
}

__device__ __forceinline__ void mma_bf16(float c[4], const uint32_t a[4],
                                         uint32_t b0, uint32_t b1) {
    asm volatile(
        "mma.sync.aligned.m16n8k16.row.col.f32.bf16.bf16.f32 "
        "{%0,%1,%2,%3},{%4,%5,%6,%7},{%8,%9},{%0,%1,%2,%3};"
        : "+f"(c[0]), "+f"(c[1]), "+f"(c[2]), "+f"(c[3])
        : "r"(a[0]), "r"(a[1]), "r"(a[2]), "r"(a[3]), "r"(b0), "r"(b1));
}

// convert float4 (4 consecutive k) into hi/lo packed pairs and store to smem
__device__ __forceinline__ void store_hilo(uint32_t* hiArr, uint32_t* loArr,
                                           int base, float4 v) {
    float hx = __bfloat162float(__float2bfloat16_rn(v.x));
    float hy = __bfloat162float(__float2bfloat16_rn(v.y));
    float hz = __bfloat162float(__float2bfloat16_rn(v.z));
    float hw = __bfloat162float(__float2bfloat16_rn(v.w));
    uint2 hi = make_uint2(pack_bf16(hx, hy), pack_bf16(hz, hw));
    uint2 lo = make_uint2(pack_bf16(v.x - hx, v.y - hy), pack_bf16(v.z - hz, v.w - hw));
    *(uint2*)&hiArr[base] = hi;
    *(uint2*)&loArr[base] = lo;
}

__global__ __launch_bounds__(256)
void gemm_mma_kernel(const float* __restrict__ A, const float* __restrict__ W,
                     const float* __restrict__ ct, const float* __restrict__ st,
                     float* __restrict__ out, int mode)
{
    __shared__ uint32_t sAhi[128 * SROW];
    __shared__ uint32_t sAlo[128 * SROW];
    __shared__ uint32_t sBhi[128 * SROW];
    __shared__ uint32_t sBlo[128 * SROW];

    const int tid = threadIdx.x;
    const int wid = tid >> 5;
    const int lid = tid & 31;
    const int wm = wid >> 2;          // 0..1
    const int wn = wid & 3;           // 0..3
    const int r  = lid >> 2;          // 0..7
    const int c4 = lid & 3;           // 0..3
    const int m0 = blockIdx.y * 128;
    const int n0 = blockIdx.x * 128;

    float C[4][4][4];
    #pragma unroll
    for (int mt = 0; mt < 4; mt++)
        #pragma unroll
        for (int nt = 0; nt < 4; nt++)
            #pragma unroll
            for (int q = 0; q < 4; q++) C[mt][nt][q] = 0.f;

    float4 ra[4], rb[4];

    // prefetch tile 0
    #pragma unroll
    for (int i = 0; i < 4; i++) {
        int idx = tid + i * 256;          // 0..1023
        int row = idx >> 3, ch = idx & 7; // 8 float4 chunks (32 floats) per row
        ra[i] = *(const float4*)&A[(size_t)(m0 + row) * DD + ch * 4];
        rb[i] = *(const float4*)&W[(size_t)(n0 + row) * DD + ch * 4];
    }
    #pragma unroll
    for (int i = 0; i < 4; i++) {
        int idx = tid + i * 256;
        int row = idx >> 3, ch = idx & 7;
        int base = row * SROW + ch * 2;
        store_hilo(sAhi, sAlo, base, ra[i]);
        store_hilo(sBhi, sBlo, base, rb[i]);
    }

    const int aoff = (wm * 64 + r) * SROW + c4;
    const int boff = (wn * 32 + r) * SROW + c4;

    for (int kt = 0; kt < 32; kt++) {
        __syncthreads();   // smem tile kt visible
        if (kt < 31) {
            int k0 = (kt + 1) * KT;
            #pragma unroll
            for (int i = 0; i < 4; i++) {
                int idx = tid + i * 256;
                int row = idx >> 3, ch = idx & 7;
                ra[i] = *(const float4*)&A[(size_t)(m0 + row) * DD + k0 + ch * 4];
                rb[i] = *(const float4*)&W[(size_t)(n0 + row) * DD + k0 + ch * 4];
            }
        }
        // MMA over tile kt: 2 k16 chunks
        #pragma unroll
        for (int kc = 0; kc < 2; kc++) {
            uint32_t bh[4][2], bl[4][2];
            #pragma unroll
            for (int nt = 0; nt < 4; nt++) {
                int bb = boff + nt * 8 * SROW + kc * 8;
                bh[nt][0] = sBhi[bb];     bh[nt][1] = sBhi[bb + 4];
                bl[nt][0] = sBlo[bb];     bl[nt][1] = sBlo[bb + 4];
            }
            #pragma unroll
            for (int mt = 0; mt < 4; mt++) {
                int ab = aoff + mt * 16 * SROW + kc * 8;
                uint32_t ah[4], al[4];
                ah[0] = sAhi[ab];             ah[1] = sAhi[ab + 8 * SROW];
                ah[2] = sAhi[ab + 4];         ah[3] = sAhi[ab + 8 * SROW + 4];
                al[0] = sAlo[ab];             al[1] = sAlo[ab + 8 * SROW];
                al[2] = sAlo[ab + 4];         al[3] = sAlo[ab + 8 * SROW + 4];
                #pragma unroll
                for (int nt = 0; nt < 4; nt++) {
                    mma_bf16(C[mt][nt], ah, bh[nt][0], bh[nt][1]);
                    mma_bf16(C[mt][nt], ah, bl[nt][0], bl[nt][1]);
                    mma_bf16(C[mt][nt], al, bh[nt][0], bh[nt][1]);
                }
            }
        }
        __syncthreads();   // all warps done reading tile kt
        if (kt < 31) {
            #pragma unroll
            for (int i = 0; i < 4; i++) {
                int idx = tid + i * 256;
                int row = idx >> 3, ch = idx & 7;
                int base = row * SROW + ch * 2;
                store_hilo(sAhi, sAlo, base, ra[i]);
                store_hilo(sBhi, sBlo, base, rb[i]);
            }
        }
    }

    // ---------------- epilogue ----------------
    #pragma unroll
    for (int mt = 0; mt < 4; mt++) {
        const int row0 = m0 + wm * 64 + mt * 16 + r;
        const int row1 = row0 + 8;
        #pragma unroll
        for (int nt = 0; nt < 4; nt++) {
            const int ncol = n0 + wn * 32 + nt * 8 + c4 * 2;
            float v00 = C[mt][nt][0], v01 = C[mt][nt][1];
            float v10 = C[mt][nt][2], v11 = C[mt][nt][3];
            if (mode == 2) {
                *(float2*)&out[(size_t)row0 * DD + ncol] = make_float2(v00, v01);
                *(float2*)&out[(size_t)row1 * DD + ncol] = make_float2(v10, v11);
            } else {
                const int h   = ncol >> 6;
                const int dk0 = ncol & 63;
                if (mode == 0) {
                    const int p = dk0 >> 1;
                    float cs0 = ct[(size_t)row0 * 32 + p], sn0 = st[(size_t)row0 * 32 + p];
                    float cs1 = ct[(size_t)row1 * 32 + p], sn1 = st[(size_t)row1 * 32 + p];
                    float t00 = cs0 * v00 - sn0 * v01;
                    float t01 = sn0 * v00 + cs0 * v01;
                    float t10 = cs1 * v10 - sn1 * v11;
                    float t11 = sn1 * v10 + cs1 * v11;
                    v00 = t00; v01 = t01; v10 = t10; v11 = t11;
                }
                const int b0r = row0 >> 11, s0 = row0 & (SS - 1);
                const int b1r = row1 >> 11, s1 = row1 & (SS - 1);
                *(float2*)&out[((size_t)(b0r * HH + h) * SS + s0) * DK + dk0] =
                    make_float2(v00, v01);
                *(float2*)&out[((size_t)(b1r * HH + h) * SS + s1) * DK + dk0] =
                    make_float2(v10, v11);
            }
        }
    }
}

// ---------------- flash attention (causal), fp32 (unchanged, known-good) -------
#define AST 68
#define ASM_BYTES (4 * 64 * AST * 4)

__global__ __launch_bounds__(256)
void attn_kernel(const float* __restrict__ qb, const float* __restrict__ kb,
                 const float* __restrict__ vb, float* __restrict__ aout)
{
    extern __shared__ float sm[];
    float* Qt = sm;
    float* Kt = sm + 64 * AST;
    float* Vs = sm + 2 * 64 * AST;
    float* Pt = sm + 3 * 64 * AST;

    const int tid = threadIdx.x;
    const int rg = tid >> 4;
    const int cg = tid & 15;
    const int qt = gridDim.x - 1 - blockIdx.x;
    const int bh = blockIdx.y;
    const int q0 = qt * 64;

    const float* qh = qb + (size_t)bh * SS * DK;
    const float* kh = kb + (size_t)bh * SS * DK;
    const float* vh = vb + (size_t)bh * SS * DK;

    #pragma unroll
    for (int it = 0; it < 4; it++) {
        int idx = tid + it * 256;
        int dq = idx >> 6;
        int r  = idx & 63;
        float4 v = *(const float4*)&qh[(size_t)(q0 + r) * DK + dq * 4];
        Qt[(dq*4+0)*AST + r] = v.x;
        Qt[(dq*4+1)*AST + r] = v.y;
        Qt[(dq*4+2)*AST + r] = v.z;
        Qt[(dq*4+3)*AST + r] = v.w;
    }

    float m_r[4], l_r[4], o[4][4];
    #pragma unroll
    for (int i = 0; i < 4; i++) {
        m_r[i] = -CUDART_INF_F; l_r[i] = 0.f;
        #pragma unroll
        for (int j = 0; j < 4; j++) o[i][j] = 0.f;
    }
    __syncthreads();

    for (int kt = 0; kt <= qt; kt++) {
        const int k0 = kt * 64;
        #pragma unroll
        for (int it = 0; it < 4; it++) {
            int idx = tid + it * 256;
            int dq = idx >> 6;
            int r  = idx & 63;
            float4 v = *(const float4*)&kh[(size_t)(k0 + r) * DK + dq * 4];
            Kt[(dq*4+0)*AST + r] = v.x;
            Kt[(dq*4+1)*AST + r] = v.y;
            Kt[(dq*4+2)*AST + r] = v.z;
            Kt[(dq*4+3)*AST + r] = v.w;
            int c  = idx >> 4;
            int dv = idx & 15;
            float4 w = *(const float4*)&vh[(size_t)(k0 + c) * DK + dv * 4];
            *(float4*)&Vs[c*AST + dv*4] = w;
        }
        __syncthreads();

        float s[4][4];
        #pragma unroll
        for (int i = 0; i < 4; i++)
            #pragma unroll
            for (int j = 0; j < 4; j++) s[i][j] = 0.f;
        #pragma unroll 8
        for (int d = 0; d < 64; d++) {
            float4 q4 = *(const float4*)&Qt[d*AST + rg*4];
            float4 k4 = *(const float4*)&Kt[d*AST + cg*4];
            float qa[4] = {q4.x, q4.y, q4.z, q4.w};
            float ka[4] = {k4.x, k4.y, k4.z, k4.w};
            #pragma unroll
            for (int i = 0; i < 4; i++)
                #pragma unroll
                for (int j = 0; j < 4; j++)
                    s[i][j] += qa[i] * ka[j];
        }

        const bool diag = (kt == qt);
        float p[4][4];
        #pragma unroll
        for (int i = 0; i < 4; i++) {
            float rm = -CUDART_INF_F;
            #pragma unroll
            for (int j = 0; j < 4; j++) {
                float v = s[i][j] * 0.125f;
                if (diag && (cg*4 + j > rg*4 + i)) v = -CUDART_INF_F;
                s[i][j] = v;
                rm = fmaxf(rm, v);
            }
            #pragma unroll
            for (int off = 1; off < 16; off <<= 1)
                rm = fmaxf(rm, __shfl_xor_sync(0xffffffffu, rm, off));
            float mn = fmaxf(m_r[i], rm);
            float a  = __expf(m_r[i] - mn);
            float ps = 0.f;
            #pragma unroll
            for (int j = 0; j < 4; j++) {
                p[i][j] = __expf(s[i][j] - mn);
                ps += p[i][j];
            }
            #pragma unroll
            for (int off = 1; off < 16; off <<= 1)
                ps += __shfl_xor_sync(0xffffffffu, ps, off);
            l_r[i] = l_r[i] * a + ps;
            m_r[i] = mn;
            #pragma unroll
            for (int j = 0; j < 4; j++) o[i][j] *= a;
        }

        #pragma unroll
        for (int j = 0; j < 4; j++)
            *(float4*)&Pt[(cg*4+j)*AST + rg*4] =
                make_float4(p[0][j], p[1][j], p[2][j], p[3][j]);
        __syncthreads();

        #pragma unroll 8
        for (int k = 0; k < 64; k++) {
            float4 p4 = *(const float4*)&Pt[k*AST + rg*4];
            float4 v4 = *(const float4*)&Vs[k*AST + cg*4];
            float pa[4] = {p4.x, p4.y, p4.z, p4.w};
            float va[4] = {v4.x, v4.y, v4.z, v4.w};
            #pragma unroll
            for (int i = 0; i < 4; i++)
                #pragma unroll
                for (int j = 0; j < 4; j++)
                    o[i][j] += pa[i] * va[j];
        }
        __syncthreads();
    }

    const int b = bh >> 4, h = bh & 15;
    #pragma unroll
    for (int i = 0; i < 4; i++) {
        float invl = 1.0f / l_r[i];
        int srow = q0 + rg*4 + i;
        float* dst = aout + ((size_t)(b * SS + srow)) * DD + h * DK + cg * 4;
        *(float4*)dst = make_float4(o[i][0]*invl, o[i][1]*invl,
                                    o[i][2]*invl, o[i][3]*invl);
    }
}

// ---------------- launch --------------------------------------------------------
extern "C" void kernel_launch(void* const* d_in, const int* in_sizes, int n_in,
                              void* d_out, int out_size)
{
    (void)in_sizes; (void)n_in; (void)out_size;
    const float* x  = (const float*)d_in[0];
    const float* Wq = (const float*)d_in[1];
    const float* Wk = (const float*)d_in[2];
    const float* Wv = (const float*)d_in[3];
    const float* Wo = (const float*)d_in[4];
    const int*   tp = (const int*)d_in[5];
    float* out = (float*)d_out;

    float *qb, *kb, *vb, *ab, *ct, *st;
    cudaGetSymbolAddress((void**)&qb, g_qbuf);
    cudaGetSymbolAddress((void**)&kb, g_kbuf);
    cudaGetSymbolAddress((void**)&vb, g_vbuf);
    cudaGetSymbolAddress((void**)&ab, g_attn);
    cudaGetSymbolAddress((void**)&ct, g_ct);
    cudaGetSymbolAddress((void**)&st, g_st);

    cudaFuncSetAttribute(attn_kernel, cudaFuncAttributeMaxDynamicSharedMemorySize, ASM_BYTES);

    rope_tab_kernel<<<(BB*SS*32 + 255) / 256, 256>>>(tp, ct, st);

    dim3 gproj(DD / 128, (BB * SS) / 128);   // (8, 32)
    gemm_mma_kernel<<<gproj, 256>>>(x, Wq, ct, st, qb, 0);
    gemm_mma_kernel<<<gproj, 256>>>(x, Wk, ct, st, kb, 0);
    gemm_mma_kernel<<<gproj, 256>>>(x, Wv, ct, st, vb, 1);

    attn_kernel<<<dim3(SS / 64, BB * HH), 256, ASM_BYTES>>>(qb, kb, vb, ab);

    gemm_mma_kernel<<<gproj, 256>>>(ab, Wo, ct, st, out, 2);
}

// round 4
// speedup vs baseline: 1.7457x; 1.4011x over previous
#include <cuda_runtime.h>
#include <cuda_bf16.h>
#include <math.h>
#include <math_constants.h>
#include <cstdint>

#define BB 2
#define SS 2048
#define DD 1024
#define HH 16
#define DK 64

// ---------------- scratch (allocation-free: __device__ globals) ----------------
__device__ float g_qbuf[BB*HH*SS*DK];   // [b*H+h][s][dk]
__device__ float g_kbuf[BB*HH*SS*DK];
__device__ float g_vbuf[BB*HH*SS*DK];
__device__ float g_attn[BB*SS*DD];      // [b][s][h*64+dk]
__device__ float g_ct[BB*SS*32];        // cos table [m][p]
__device__ float g_st[BB*SS*32];        // sin table [m][p]

// ======================= RoPE table precompute ==================================
__global__ void rope_tab_kernel(const int* __restrict__ tp, float* __restrict__ ct,
                                float* __restrict__ st)
{
    int idx = blockIdx.x * blockDim.x + threadIdx.x;  // m*32 + p
    if (idx >= BB*SS*32) return;
    int m = idx >> 5;
    int p = idx & 31;
    float inv = powf(10000.0f, -(float)(2*p) * (1.0f/64.0f));
    float freq = (float)tp[m] * inv;
    float sn, cs;
    sincosf(freq, &sn, &cs);
    ct[idx] = cs;
    st[idx] = sn;
}

// ======================= shared helpers ========================================
__device__ __forceinline__ uint32_t pack_bf16(float a, float b) {
    __nv_bfloat16 ha = __float2bfloat16_rn(a);
    __nv_bfloat16 hb = __float2bfloat16_rn(b);
    return (uint32_t)__bfloat16_as_ushort(ha) | ((uint32_t)__bfloat16_as_ushort(hb) << 16);
}

__device__ __forceinline__ void mma_bf16(float c[4], const uint32_t a[4],
                                         uint32_t b0, uint32_t b1) {
    asm volatile(
        "mma.sync.aligned.m16n8k16.row.col.f32.bf16.bf16.f32 "
        "{%0,%1,%2,%3},{%4,%5,%6,%7},{%8,%9},{%0,%1,%2,%3};"
        : "+f"(c[0]), "+f"(c[1]), "+f"(c[2]), "+f"(c[3])
        : "r"(a[0]), "r"(a[1]), "r"(a[2]), "r"(a[3]), "r"(b0), "r"(b1));
}

// split float pair into packed bf16 hi + lo words, store as uint2
__device__ __forceinline__ void store_hilo(uint32_t* hiArr, uint32_t* loArr,
                                           int base, float4 v) {
    float hx = __bfloat162float(__float2bfloat16_rn(v.x));
    float hy = __bfloat162float(__float2bfloat16_rn(v.y));
    float hz = __bfloat162float(__float2bfloat16_rn(v.z));
    float hw = __bfloat162float(__float2bfloat16_rn(v.w));
    uint2 hi = make_uint2(pack_bf16(hx, hy), pack_bf16(hz, hw));
    uint2 lo = make_uint2(pack_bf16(v.x - hx, v.y - hy), pack_bf16(v.z - hz, v.w - hw));
    *(uint2*)&hiArr[base] = hi;
    *(uint2*)&loArr[base] = lo;
}

// fast exp2 on FMA pipe (no MUFU): magic round + deg-5 poly + exponent add
__device__ __forceinline__ float exp2a(float x) {
    x = fmaxf(x, -126.0f);
    float z = x + 12582912.0f;                 // 1.5 * 2^23
    uint32_t iz = __float_as_uint(z);
    float f = x - (z - 12582912.0f);           // f in [-0.5, 0.5]
    float p = 0.0013333558f;
    p = fmaf(p, f, 0.0096180885f);
    p = fmaf(p, f, 0.0555041087f);
    p = fmaf(p, f, 0.2402265069f);
    p = fmaf(p, f, 0.6931471806f);
    p = fmaf(p, f, 1.0f);
    return __uint_as_float(__float_as_uint(p) + (iz << 23));
}

// ======================= mma.sync bf16 hi/lo GEMM (round-3, unchanged) =========
#define KT 32
#define SROW 20

__global__ __launch_bounds__(256)
void gemm_mma_kernel(const float* __restrict__ A, const float* __restrict__ W,
                     const float* __restrict__ ct, const float* __restrict__ st,
                     float* __restrict__ out, int mode)
{
    __shared__ uint32_t sAhi[128 * SROW];
    __shared__ uint32_t sAlo[128 * SROW];
    __shared__ uint32_t sBhi[128 * SROW];
    __shared__ uint32_t sBlo[128 * SROW];

    const int tid = threadIdx.x;
    const int wid = tid >> 5;
    const int lid = tid & 31;
    const int wm = wid >> 2;
    const int wn = wid & 3;
    const int r  = lid >> 2;
    const int c4 = lid & 3;
    const int m0 = blockIdx.y * 128;
    const int n0 = blockIdx.x * 128;

    float C[4][4][4];
    #pragma unroll
    for (int mt = 0; mt < 4; mt++)
        #pragma unroll
        for (int nt = 0; nt < 4; nt++)
            #pragma unroll
            for (int q = 0; q < 4; q++) C[mt][nt][q] = 0.f;

    float4 ra[4], rb[4];

    #pragma unroll
    for (int i = 0; i < 4; i++) {
        int idx = tid + i * 256;
        int row = idx >> 3, ch = idx & 7;
        ra[i] = *(const float4*)&A[(size_t)(m0 + row) * DD + ch * 4];
        rb[i] = *(const float4*)&W[(size_t)(n0 + row) * DD + ch * 4];
    }
    #pragma unroll
    for (int i = 0; i < 4; i++) {
        int idx = tid + i * 256;
        int row = idx >> 3, ch = idx & 7;
        int base = row * SROW + ch * 2;
        store_hilo(sAhi, sAlo, base, ra[i]);
        store_hilo(sBhi, sBlo, base, rb[i]);
    }

    const int aoff = (wm * 64 + r) * SROW + c4;
    const int boff = (wn * 32 + r) * SROW + c4;

    for (int kt = 0; kt < 32; kt++) {
        __syncthreads();
        if (kt < 31) {
            int k0 = (kt + 1) * KT;
            #pragma unroll
            for (int i = 0; i < 4; i++) {
                int idx = tid + i * 256;
                int row = idx >> 3, ch = idx & 7;
                ra[i] = *(const float4*)&A[(size_t)(m0 + row) * DD + k0 + ch * 4];
                rb[i] = *(const float4*)&W[(size_t)(n0 + row) * DD + k0 + ch * 4];
            }
        }
        #pragma unroll
        for (int kc = 0; kc < 2; kc++) {
            uint32_t bh[4][2], bl[4][2];
            #pragma unroll
            for (int nt = 0; nt < 4; nt++) {
                int bb = boff + nt * 8 * SROW + kc * 8;
                bh[nt][0] = sBhi[bb];     bh[nt][1] = sBhi[bb + 4];
                bl[nt][0] = sBlo[bb];     bl[nt][1] = sBlo[bb + 4];
            }
            #pragma unroll
            for (int mt = 0; mt < 4; mt++) {
                int ab = aoff + mt * 16 * SROW + kc * 8;
                uint32_t ah[4], al[4];
                ah[0] = sAhi[ab];             ah[1] = sAhi[ab + 8 * SROW];
                ah[2] = sAhi[ab + 4];         ah[3] = sAhi[ab + 8 * SROW + 4];
                al[0] = sAlo[ab];             al[1] = sAlo[ab + 8 * SROW];
                al[2] = sAlo[ab + 4];         al[3] = sAlo[ab + 8 * SROW + 4];
                #pragma unroll
                for (int nt = 0; nt < 4; nt++) {
                    mma_bf16(C[mt][nt], ah, bh[nt][0], bh[nt][1]);
                    mma_bf16(C[mt][nt], ah, bl[nt][0], bl[nt][1]);
                    mma_bf16(C[mt][nt], al, bh[nt][0], bh[nt][1]);
                }
            }
        }
        __syncthreads();
        if (kt < 31) {
            #pragma unroll
            for (int i = 0; i < 4; i++) {
                int idx = tid + i * 256;
                int row = idx >> 3, ch = idx & 7;
                int base = row * SROW + ch * 2;
                store_hilo(sAhi, sAlo, base, ra[i]);
                store_hilo(sBhi, sBlo, base, rb[i]);
            }
        }
    }

    #pragma unroll
    for (int mt = 0; mt < 4; mt++) {
        const int row0 = m0 + wm * 64 + mt * 16 + r;
        const int row1 = row0 + 8;
        #pragma unroll
        for (int nt = 0; nt < 4; nt++) {
            const int ncol = n0 + wn * 32 + nt * 8 + c4 * 2;
            float v00 = C[mt][nt][0], v01 = C[mt][nt][1];
            float v10 = C[mt][nt][2], v11 = C[mt][nt][3];
            if (mode == 2) {
                *(float2*)&out[(size_t)row0 * DD + ncol] = make_float2(v00, v01);
                *(float2*)&out[(size_t)row1 * DD + ncol] = make_float2(v10, v11);
            } else {
                const int h   = ncol >> 6;
                const int dk0 = ncol & 63;
                if (mode == 0) {
                    const int p = dk0 >> 1;
                    float cs0 = ct[(size_t)row0 * 32 + p], sn0 = st[(size_t)row0 * 32 + p];
                    float cs1 = ct[(size_t)row1 * 32 + p], sn1 = st[(size_t)row1 * 32 + p];
                    float t00 = cs0 * v00 - sn0 * v01;
                    float t01 = sn0 * v00 + cs0 * v01;
                    float t10 = cs1 * v10 - sn1 * v11;
                    float t11 = sn1 * v10 + cs1 * v11;
                    v00 = t00; v01 = t01; v10 = t10; v11 = t11;
                }
                const int b0r = row0 >> 11, s0 = row0 & (SS - 1);
                const int b1r = row1 >> 11, s1 = row1 & (SS - 1);
                *(float2*)&out[((size_t)(b0r * HH + h) * SS + s0) * DK + dk0] =
                    make_float2(v00, v01);
                *(float2*)&out[((size_t)(b1r * HH + h) * SS + s1) * DK + dk0] =
                    make_float2(v10, v11);
            }
        }
    }
}

// ======================= mma.sync flash attention ==============================
// CTA: 128 q-rows x (kt loop of 128 keys). 256 threads = 8 warps, warp = 16 rows.
// QK^T: 3-pass hi/lo. PV: 3-pass (PhVh + PhVl + PlVh). exp on FMA pipe.
#define QST 36    // Q/K smem row stride (uint32), 36 % 32 == 4 -> conflict-free
#define VST 68    // V/P smem row stride

#define UQH 0
#define UQL (UQH + 128*QST)
#define UKH (UQL + 128*QST)
#define UKL (UKH + 128*QST)
#define UVH (UKL + 128*QST)
#define UVL (UVH + 64*VST)
#define UPH (UVL + 64*VST)
#define UPL (UPH + 128*VST)
#define ATTN_SMEM_U32 (UPL + 128*VST)
#define ATTN_SMEM_BYTES (ATTN_SMEM_U32 * 4)

__global__ __launch_bounds__(256)
void attn_mma_kernel(const float* __restrict__ qb, const float* __restrict__ kb,
                     const float* __restrict__ vb, float* __restrict__ aout)
{
    extern __shared__ uint32_t su[];
    uint32_t* sQh = su + UQH;
    uint32_t* sQl = su + UQL;
    uint32_t* sKh = su + UKH;
    uint32_t* sKl = su + UKL;
    uint32_t* sVh = su + UVH;
    uint32_t* sVl = su + UVL;
    uint32_t* sPh = su + UPH;
    uint32_t* sPl = su + UPL;

    const int tid = threadIdx.x;
    const int wid = tid >> 5;
    const int lid = tid & 31;
    const int r   = lid >> 2;       // 0..7
    const int c4  = lid & 3;        // 0..3
    const int bh  = blockIdx.y;
    const int qt  = gridDim.x - 1 - blockIdx.x;  // heavy tiles first
    const int q0  = qt * 128;

    const float* qh = qb + (size_t)bh * SS * DK;
    const float* kh = kb + (size_t)bh * SS * DK;
    const float* vh = vb + (size_t)bh * SS * DK;

    // load Q tile, scaled by 1/8 * log2(e) so S is in exp2 domain
    const float CSC = 0.125f * 1.44269504088896f;
    #pragma unroll
    for (int it = 0; it < 8; it++) {
        int idx = tid + it * 256;       // 0..2047
        int row = idx >> 4, ch = idx & 15;
        float4 v = *(const float4*)&qh[(size_t)(q0 + row) * DK + ch * 4];
        v.x *= CSC; v.y *= CSC; v.z *= CSC; v.w *= CSC;
        store_hilo(sQh, sQl, row * QST + ch * 2, v);
    }

    float mrow[2] = {-CUDART_INF_F, -CUDART_INF_F};
    float lrow[2] = {0.f, 0.f};
    float O[8][4];
    #pragma unroll
    for (int i = 0; i < 8; i++)
        #pragma unroll
        for (int j = 0; j < 4; j++) O[i][j] = 0.f;

    const int abase = (wid * 16 + r) * QST + c4;
    const int pbase = (wid * 16 + r) * VST + c4;
    const int cpr  = tid & 63;       // key pair for V transpose
    const int dgrp = tid >> 6;       // dk group of 16

    for (int kt = 0; kt <= qt; kt++) {
        const int k0 = kt * 128;
        __syncthreads();   // previous iter's K/V reads complete

        // K tile
        #pragma unroll
        for (int it = 0; it < 8; it++) {
            int idx = tid + it * 256;
            int row = idx >> 4, ch = idx & 15;
            float4 v = *(const float4*)&kh[(size_t)(k0 + row) * DK + ch * 4];
            store_hilo(sKh, sKl, row * QST + ch * 2, v);
        }
        // V tile, transposed to [dk][key]
        #pragma unroll
        for (int dd = 0; dd < 4; dd++) {
            int d = dgrp * 16 + dd * 4;
            float4 v0 = *(const float4*)&vh[(size_t)(k0 + 2*cpr)     * DK + d];
            float4 v1 = *(const float4*)&vh[(size_t)(k0 + 2*cpr + 1) * DK + d];
            float a0[4] = {v0.x, v0.y, v0.z, v0.w};
            float a1[4] = {v1.x, v1.y, v1.z, v1.w};
            #pragma unroll
            for (int e = 0; e < 4; e++) {
                float h0 = __bfloat162float(__float2bfloat16_rn(a0[e]));
                float h1 = __bfloat162float(__float2bfloat16_rn(a1[e]));
                sVh[(d + e) * VST + cpr] = pack_bf16(h0, h1);
                sVl[(d + e) * VST + cpr] = pack_bf16(a0[e] - h0, a1[e] - h1);
            }
        }
        __syncthreads();

        // ---- S = Q K^T (3-pass hi/lo), warp rows wid*16..+16, cols 0..127 ----
        float Sv[16][4];
        #pragma unroll
        for (int nt = 0; nt < 16; nt++)
            #pragma unroll
            for (int q = 0; q < 4; q++) Sv[nt][q] = 0.f;

        #pragma unroll
        for (int kc = 0; kc < 4; kc++) {
            int ao = abase + kc * 8;
            uint32_t ah[4], al[4];
            ah[0] = sQh[ao];              ah[1] = sQh[ao + 8*QST];
            ah[2] = sQh[ao + 4];          ah[3] = sQh[ao + 8*QST + 4];
            al[0] = sQl[ao];              al[1] = sQl[ao + 8*QST];
            al[2] = sQl[ao + 4];          al[3] = sQl[ao + 8*QST + 4];
            #pragma unroll
            for (int nt = 0; nt < 16; nt++) {
                int bo = (nt * 8 + r) * QST + kc * 8 + c4;
                uint32_t bh0 = sKh[bo], bh1 = sKh[bo + 4];
                uint32_t bl0 = sKl[bo], bl1 = sKl[bo + 4];
                mma_bf16(Sv[nt], ah, bh0, bh1);
                mma_bf16(Sv[nt], ah, bl0, bl1);
                mma_bf16(Sv[nt], al, bh0, bh1);
            }
        }

        // ---- causal mask on diagonal tile ----
        if (kt == qt) {
            int row0 = wid * 16 + r;
            int row1 = row0 + 8;
            #pragma unroll
            for (int nt = 0; nt < 16; nt++) {
                int col = nt * 8 + c4 * 2;
                if (col     > row0) Sv[nt][0] = -1e30f;
                if (col + 1 > row0) Sv[nt][1] = -1e30f;
                if (col     > row1) Sv[nt][2] = -1e30f;
                if (col + 1 > row1) Sv[nt][3] = -1e30f;
            }
        }

        // ---- online softmax (exp2 domain), per row-half ----
        #pragma unroll
        for (int hrow = 0; hrow < 2; hrow++) {
            float tm = -CUDART_INF_F;
            #pragma unroll
            for (int nt = 0; nt < 16; nt++) {
                tm = fmaxf(tm, Sv[nt][2*hrow]);
                tm = fmaxf(tm, Sv[nt][2*hrow + 1]);
            }
            tm = fmaxf(tm, __shfl_xor_sync(0xffffffffu, tm, 1));
            tm = fmaxf(tm, __shfl_xor_sync(0xffffffffu, tm, 2));
            float mn = fmaxf(mrow[hrow], tm);
            float alpha = exp2a(mrow[hrow] - mn);
            float ps = 0.f;
            #pragma unroll
            for (int nt = 0; nt < 16; nt++) {
                float p0 = exp2a(Sv[nt][2*hrow]     - mn);
                float p1 = exp2a(Sv[nt][2*hrow + 1] - mn);
                Sv[nt][2*hrow]     = p0;
                Sv[nt][2*hrow + 1] = p1;
                ps += p0 + p1;
            }
            ps += __shfl_xor_sync(0xffffffffu, ps, 1);
            ps += __shfl_xor_sync(0xffffffffu, ps, 2);
            lrow[hrow] = lrow[hrow] * alpha + ps;
            mrow[hrow] = mn;
            #pragma unroll
            for (int nt2 = 0; nt2 < 8; nt2++) {
                O[nt2][2*hrow]     *= alpha;
                O[nt2][2*hrow + 1] *= alpha;
            }
        }

        // ---- store P hi/lo (warp-private rows) ----
        #pragma unroll
        for (int nt = 0; nt < 16; nt++) {
            int w0 = (wid * 16 + r) * VST + nt * 4 + c4;
            float p0 = Sv[nt][0], p1 = Sv[nt][1];
            float h0 = __bfloat162float(__float2bfloat16_rn(p0));
            float h1 = __bfloat162float(__float2bfloat16_rn(p1));
            sPh[w0] = pack_bf16(h0, h1);
            sPl[w0] = pack_bf16(p0 - h0, p1 - h1);
            float p2 = Sv[nt][2], p3 = Sv[nt][3];
            float h2 = __bfloat162float(__float2bfloat16_rn(p2));
            float h3 = __bfloat162float(__float2bfloat16_rn(p3));
            sPh[w0 + 8*VST] = pack_bf16(h2, h3);
            sPl[w0 + 8*VST] = pack_bf16(p2 - h2, p3 - h3);
        }
        __syncwarp();

        // ---- O += P V (3-pass) ----
        #pragma unroll
        for (int kc2 = 0; kc2 < 8; kc2++) {
            int po = pbase + kc2 * 8;
            uint32_t ph[4], pl[4];
            ph[0] = sPh[po];              ph[1] = sPh[po + 8*VST];
            ph[2] = sPh[po + 4];          ph[3] = sPh[po + 8*VST + 4];
            pl[0] = sPl[po];              pl[1] = sPl[po + 8*VST];
            pl[2] = sPl[po + 4];          pl[3] = sPl[po + 8*VST + 4];
            #pragma unroll
            for (int nt2 = 0; nt2 < 8; nt2++) {
                int vo = (nt2 * 8 + r) * VST + kc2 * 8 + c4;
                uint32_t vh0 = sVh[vo], vh1 = sVh[vo + 4];
                uint32_t vl0 = sVl[vo], vl1 = sVl[vo + 4];
                mma_bf16(O[nt2], ph, vh0, vh1);
                mma_bf16(O[nt2], ph, vl0, vl1);
                mma_bf16(O[nt2], pl, vh0, vh1);
            }
        }
    }

    // ---- normalize + write out ----
    const int b = bh >> 4, h = bh & 15;
    const float inv0 = 1.0f / lrow[0];
    const float inv1 = 1.0f / lrow[1];
    const int row0g = q0 + wid * 16 + r;
    const int row1g = row0g + 8;
    #pragma unroll
    for (int nt2 = 0; nt2 < 8; nt2++) {
        int col = h * DK + nt2 * 8 + c4 * 2;
        *(float2*)&aout[(size_t)(b * SS + row0g) * DD + col] =
            make_float2(O[nt2][0] * inv0, O[nt2][1] * inv0);
        *(float2*)&aout[(size_t)(b * SS + row1g) * DD + col] =
            make_float2(O[nt2][2] * inv1, O[nt2][3] * inv1);
    }
}

// ---------------- launch --------------------------------------------------------
extern "C" void kernel_launch(void* const* d_in, const int* in_sizes, int n_in,
                              void* d_out, int out_size)
{
    (void)in_sizes; (void)n_in; (void)out_size;
    const float* x  = (const float*)d_in[0];
    const float* Wq = (const float*)d_in[1];
    const float* Wk = (const float*)d_in[2];
    const float* Wv = (const float*)d_in[3];
    const float* Wo = (const float*)d_in[4];
    const int*   tp = (const int*)d_in[5];
    float* out = (float*)d_out;

    float *qb, *kb, *vb, *ab, *ct, *st;
    cudaGetSymbolAddress((void**)&qb, g_qbuf);
    cudaGetSymbolAddress((void**)&kb, g_kbuf);
    cudaGetSymbolAddress((void**)&vb, g_vbuf);
    cudaGetSymbolAddress((void**)&ab, g_attn);
    cudaGetSymbolAddress((void**)&ct, g_ct);
    cudaGetSymbolAddress((void**)&st, g_st);

    cudaFuncSetAttribute(attn_mma_kernel, cudaFuncAttributeMaxDynamicSharedMemorySize,
                         ATTN_SMEM_BYTES);

    rope_tab_kernel<<<(BB*SS*32 + 255) / 256, 256>>>(tp, ct, st);

    dim3 gproj(DD / 128, (BB * SS) / 128);   // (8, 32)
    gemm_mma_kernel<<<gproj, 256>>>(x, Wq, ct, st, qb, 0);
    gemm_mma_kernel<<<gproj, 256>>>(x, Wk, ct, st, kb, 0);
    gemm_mma_kernel<<<gproj, 256>>>(x, Wv, ct, st, vb, 1);

    attn_mma_kernel<<<dim3(SS / 128, BB * HH), 256, ATTN_SMEM_BYTES>>>(qb, kb, vb, ab);

    gemm_mma_kernel<<<gproj, 256>>>(ab, Wo, ct, st, out, 2);
}

// round 5
// speedup vs baseline: 1.9902x; 1.1400x over previous
#include <cuda_runtime.h>
#include <cuda_bf16.h>
#include <math.h>
#include <math_constants.h>
#include <cstdint>

#define BB 2
#define SS 2048
#define DD 1024
#define HH 16
#define DK 64

// ---------------- scratch (allocation-free: __device__ globals) ----------------
__device__ float g_qbuf[BB*HH*SS*DK];
__device__ float g_kbuf[BB*HH*SS*DK];
__device__ float g_vbuf[BB*HH*SS*DK];
__device__ float g_ct[BB*SS*32];
__device__ float g_st[BB*SS*32];
// bf16 hi/lo mirrors
__device__ __nv_bfloat16 g_xhi[BB*SS*DD], g_xlo[BB*SS*DD];
__device__ __nv_bfloat16 g_wqhi[DD*DD],  g_wqlo[DD*DD];
__device__ __nv_bfloat16 g_wkhi[DD*DD],  g_wklo[DD*DD];
__device__ __nv_bfloat16 g_wvhi[DD*DD],  g_wvlo[DD*DD];
__device__ __nv_bfloat16 g_wohi[DD*DD],  g_wolo[DD*DD];
__device__ __nv_bfloat16 g_abhi[BB*SS*DD], g_ablo[BB*SS*DD];

// ======================= helpers ================================================
__device__ __forceinline__ uint32_t smem_u32(const void* p) {
    uint32_t a;
    asm("{ .reg .u64 t; cvta.to.shared.u64 t, %1; cvt.u32.u64 %0, t; }" : "=r"(a) : "l"(p));
    return a;
}
__device__ __forceinline__ uint32_t pack_bf16(float a, float b) {
    __nv_bfloat16 ha = __float2bfloat16_rn(a);
    __nv_bfloat16 hb = __float2bfloat16_rn(b);
    return (uint32_t)__bfloat16_as_ushort(ha) | ((uint32_t)__bfloat16_as_ushort(hb) << 16);
}
__device__ __forceinline__ void mma_bf16(float c[4], const uint32_t a[4],
                                         uint32_t b0, uint32_t b1) {
    asm volatile(
        "mma.sync.aligned.m16n8k16.row.col.f32.bf16.bf16.f32 "
        "{%0,%1,%2,%3},{%4,%5,%6,%7},{%8,%9},{%0,%1,%2,%3};"
        : "+f"(c[0]), "+f"(c[1]), "+f"(c[2]), "+f"(c[3])
        : "r"(a[0]), "r"(a[1]), "r"(a[2]), "r"(a[3]), "r"(b0), "r"(b1));
}
__device__ __forceinline__ void store_hilo(uint32_t* hiArr, uint32_t* loArr,
                                           int base, float4 v) {
    float hx = __bfloat162float(__float2bfloat16_rn(v.x));
    float hy = __bfloat162float(__float2bfloat16_rn(v.y));
    float hz = __bfloat162float(__float2bfloat16_rn(v.z));
    float hw = __bfloat162float(__float2bfloat16_rn(v.w));
    uint2 hi = make_uint2(pack_bf16(hx, hy), pack_bf16(hz, hw));
    uint2 lo = make_uint2(pack_bf16(v.x - hx, v.y - hy), pack_bf16(v.z - hz, v.w - hw));
    *(uint2*)&hiArr[base] = hi;
    *(uint2*)&loArr[base] = lo;
}
// fast exp2 on FMA pipe
__device__ __forceinline__ float exp2a(float x) {
    x = fmaxf(x, -126.0f);
    float z = x + 12582912.0f;
    uint32_t iz = __float_as_uint(z);
    float f = x - (z - 12582912.0f);
    float p = 0.0013333558f;
    p = fmaf(p, f, 0.0096180885f);
    p = fmaf(p, f, 0.0555041087f);
    p = fmaf(p, f, 0.2402265069f);
    p = fmaf(p, f, 0.6931471806f);
    p = fmaf(p, f, 1.0f);
    return __uint_as_float(__float_as_uint(p) + (iz << 23));
}
__device__ __forceinline__ void cp16(uint32_t dst, const void* src) {
    asm volatile("cp.async.ca.shared.global [%0], [%1], 16;" :: "r"(dst), "l"(src));
}

// ======================= pre-pass: f32 -> bf16 hi/lo ============================
__global__ void cvt_hilo_kernel(const float* __restrict__ src,
                                __nv_bfloat16* __restrict__ hi,
                                __nv_bfloat16* __restrict__ lo, int n4)
{
    int idx = blockIdx.x * blockDim.x + threadIdx.x;
    if (idx >= n4) return;
    float4 v = *(const float4*)&src[idx * 4];
    float hx = __bfloat162float(__float2bfloat16_rn(v.x));
    float hy = __bfloat162float(__float2bfloat16_rn(v.y));
    float hz = __bfloat162float(__float2bfloat16_rn(v.z));
    float hw = __bfloat162float(__float2bfloat16_rn(v.w));
    *(uint2*)&hi[idx * 4] = make_uint2(pack_bf16(hx, hy), pack_bf16(hz, hw));
    *(uint2*)&lo[idx * 4] = make_uint2(pack_bf16(v.x - hx, v.y - hy),
                                       pack_bf16(v.z - hz, v.w - hw));
}

// ======================= RoPE table =============================================
__global__ void rope_tab_kernel(const int* __restrict__ tp, float* __restrict__ ct,
                                float* __restrict__ st)
{
    int idx = blockIdx.x * blockDim.x + threadIdx.x;
    if (idx >= BB*SS*32) return;
    int m = idx >> 5;
    int p = idx & 31;
    float inv = powf(10000.0f, -(float)(2*p) * (1.0f/64.0f));
    float freq = (float)tp[m] * inv;
    float sn, cs;
    sincosf(freq, &sn, &cs);
    ct[idx] = cs;
    st[idx] = sn;
}

// ======================= GEMM v2: bf16 hi/lo in gmem, cp.async double-buffer ====
// C[4096,1024] = A @ B^T; A,B already split hi/lo bf16, row-major K-contiguous.
#define SROW 20
#define G2_ARR 2560                    // 128*SROW uint32 per array
#define G2_STAGE (4*G2_ARR)            // Ahi,Alo,Bhi,Blo
#define G2_SMEM_BYTES (2*G2_STAGE*4)   // 81920 B

__global__ __launch_bounds__(256)
void gemm_mma2_kernel(const __nv_bfloat16* __restrict__ Ahi, const __nv_bfloat16* __restrict__ Alo,
                      const __nv_bfloat16* __restrict__ Bh,  const __nv_bfloat16* __restrict__ Bl,
                      const float* __restrict__ ct, const float* __restrict__ st,
                      float* __restrict__ out, int mode)
{
    extern __shared__ uint32_t su2[];
    const uint32_t sbase = smem_u32(su2);

    const int tid = threadIdx.x;
    const int wid = tid >> 5;
    const int lid = tid & 31;
    const int wm = wid >> 2;
    const int wn = wid & 3;
    const int r  = lid >> 2;
    const int c4 = lid & 3;
    const int m0 = blockIdx.y * 128;
    const int n0 = blockIdx.x * 128;

    const int prow = tid >> 2;          // 0..63 base row for cp.async
    const int pch  = tid & 3;           // 16B chunk

    float C[4][4][4];
    #pragma unroll
    for (int mt = 0; mt < 4; mt++)
        #pragma unroll
        for (int nt = 0; nt < 4; nt++)
            #pragma unroll
            for (int q = 0; q < 4; q++) C[mt][nt][q] = 0.f;

    // prefetch stage for tile kt into buffer st2
    auto prefetch = [&](int kt, int st2) {
        const int k0 = kt * 32;
        #pragma unroll
        for (int i = 0; i < 2; i++) {
            int row = prow + i * 64;
            uint32_t d = sbase + (uint32_t)(st2 * G2_STAGE + row * SROW + pch * 4) * 4u;
            size_t goA = (size_t)(m0 + row) * DD + k0 + pch * 8;
            size_t goB = (size_t)(n0 + row) * DD + k0 + pch * 8;
            cp16(d,                 Ahi + goA);
            cp16(d + G2_ARR * 4u,   Alo + goA);
            cp16(d + 2u*G2_ARR*4u,  Bh  + goB);
            cp16(d + 3u*G2_ARR*4u,  Bl  + goB);
        }
        asm volatile("cp.async.commit_group;" ::: "memory");
    };

    prefetch(0, 0);

    const int aoff = (wm * 64 + r) * SROW + c4;
    const int boff = (wn * 32 + r) * SROW + c4;

    for (int kt = 0; kt < 32; kt++) {
        asm volatile("cp.async.wait_group 0;" ::: "memory");
        __syncthreads();
        if (kt < 31) prefetch(kt + 1, (kt + 1) & 1);

        uint32_t* sAhi = su2 + (kt & 1) * G2_STAGE;
        uint32_t* sAlo = sAhi + G2_ARR;
        uint32_t* sBhi = sAlo + G2_ARR;
        uint32_t* sBlo = sBhi + G2_ARR;

        #pragma unroll
        for (int kc = 0; kc < 2; kc++) {
            uint32_t bh[4][2], bl[4][2];
            #pragma unroll
            for (int nt = 0; nt < 4; nt++) {
                int bb = boff + nt * 8 * SROW + kc * 8;
                bh[nt][0] = sBhi[bb];     bh[nt][1] = sBhi[bb + 4];
                bl[nt][0] = sBlo[bb];     bl[nt][1] = sBlo[bb + 4];
            }
            #pragma unroll
            for (int mt = 0; mt < 4; mt++) {
                int ab = aoff + mt * 16 * SROW + kc * 8;
                uint32_t ah[4], al[4];
                ah[0] = sAhi[ab];             ah[1] = sAhi[ab + 8 * SROW];
                ah[2] = sAhi[ab + 4];         ah[3] = sAhi[ab + 8 * SROW + 4];
                al[0] = sAlo[ab];             al[1] = sAlo[ab + 8 * SROW];
                al[2] = sAlo[ab + 4];         al[3] = sAlo[ab + 8 * SROW + 4];
                #pragma unroll
                for (int nt = 0; nt < 4; nt++) {
                    mma_bf16(C[mt][nt], ah, bh[nt][0], bh[nt][1]);
                    mma_bf16(C[mt][nt], ah, bl[nt][0], bl[nt][1]);
                    mma_bf16(C[mt][nt], al, bh[nt][0], bh[nt][1]);
                }
            }
        }
    }

    // ---------------- epilogue ----------------
    #pragma unroll
    for (int mt = 0; mt < 4; mt++) {
        const int row0 = m0 + wm * 64 + mt * 16 + r;
        const int row1 = row0 + 8;
        #pragma unroll
        for (int nt = 0; nt < 4; nt++) {
            const int ncol = n0 + wn * 32 + nt * 8 + c4 * 2;
            float v00 = C[mt][nt][0], v01 = C[mt][nt][1];
            float v10 = C[mt][nt][2], v11 = C[mt][nt][3];
            if (mode == 2) {
                *(float2*)&out[(size_t)row0 * DD + ncol] = make_float2(v00, v01);
                *(float2*)&out[(size_t)row1 * DD + ncol] = make_float2(v10, v11);
            } else {
                const int h   = ncol >> 6;
                const int dk0 = ncol & 63;
                if (mode == 0) {
                    const int p = dk0 >> 1;
                    float cs0 = ct[(size_t)row0 * 32 + p], sn0 = st[(size_t)row0 * 32 + p];
                    float cs1 = ct[(size_t)row1 * 32 + p], sn1 = st[(size_t)row1 * 32 + p];
                    float t00 = cs0 * v00 - sn0 * v01;
                    float t01 = sn0 * v00 + cs0 * v01;
                    float t10 = cs1 * v10 - sn1 * v11;
                    float t11 = sn1 * v10 + cs1 * v11;
                    v00 = t00; v01 = t01; v10 = t10; v11 = t11;
                }
                const int b0r = row0 >> 11, s0 = row0 & (SS - 1);
                const int b1r = row1 >> 11, s1 = row1 & (SS - 1);
                *(float2*)&out[((size_t)(b0r * HH + h) * SS + s0) * DK + dk0] =
                    make_float2(v00, v01);
                *(float2*)&out[((size_t)(b1r * HH + h) * SS + s1) * DK + dk0] =
                    make_float2(v10, v11);
            }
        }
    }
}

// ======================= mma.sync flash attention ==============================
#define QST 36
#define VST 68
#define UQH 0
#define UQL (UQH + 128*QST)
#define UKH (UQL + 128*QST)
#define UKL (UKH + 128*QST)
#define UVH (UKL + 128*QST)
#define UVL (UVH + 64*VST)
#define UPH (UVL + 64*VST)
#define UPL (UPH + 128*VST)
#define ATTN_SMEM_U32 (UPL + 128*VST)
#define ATTN_SMEM_BYTES (ATTN_SMEM_U32 * 4)

__global__ __launch_bounds__(256)
void attn_mma_kernel(const float* __restrict__ qb, const float* __restrict__ kb,
                     const float* __restrict__ vb,
                     __nv_bfloat16* __restrict__ ohi, __nv_bfloat16* __restrict__ olo)
{
    extern __shared__ uint32_t su[];
    uint32_t* sQh = su + UQH;
    uint32_t* sQl = su + UQL;
    uint32_t* sKh = su + UKH;
    uint32_t* sKl = su + UKL;
    uint32_t* sVh = su + UVH;
    uint32_t* sVl = su + UVL;
    uint32_t* sPh = su + UPH;
    uint32_t* sPl = su + UPL;

    const int tid = threadIdx.x;
    const int wid = tid >> 5;
    const int lid = tid & 31;
    const int r   = lid >> 2;
    const int c4  = lid & 3;
    const int bh  = blockIdx.y;
    const int qt  = gridDim.x - 1 - blockIdx.x;
    const int q0  = qt * 128;

    const float* qh = qb + (size_t)bh * SS * DK;
    const float* kh = kb + (size_t)bh * SS * DK;
    const float* vh = vb + (size_t)bh * SS * DK;

    const float CSC = 0.125f * 1.44269504088896f;
    #pragma unroll
    for (int it = 0; it < 8; it++) {
        int idx = tid + it * 256;
        int row = idx >> 4, ch = idx & 15;
        float4 v = *(const float4*)&qh[(size_t)(q0 + row) * DK + ch * 4];
        v.x *= CSC; v.y *= CSC; v.z *= CSC; v.w *= CSC;
        store_hilo(sQh, sQl, row * QST + ch * 2, v);
    }

    float mrow[2] = {-CUDART_INF_F, -CUDART_INF_F};
    float lrow[2] = {0.f, 0.f};
    float O[8][4];
    #pragma unroll
    for (int i = 0; i < 8; i++)
        #pragma unroll
        for (int j = 0; j < 4; j++) O[i][j] = 0.f;

    const int abase = (wid * 16 + r) * QST + c4;
    const int pbase = (wid * 16 + r) * VST + c4;
    const int cpr  = tid & 63;
    const int dgrp = tid >> 6;

    for (int kt = 0; kt <= qt; kt++) {
        const int k0 = kt * 128;
        __syncthreads();

        #pragma unroll
        for (int it = 0; it < 8; it++) {
            int idx = tid + it * 256;
            int row = idx >> 4, ch = idx & 15;
            float4 v = *(const float4*)&kh[(size_t)(k0 + row) * DK + ch * 4];
            store_hilo(sKh, sKl, row * QST + ch * 2, v);
        }
        #pragma unroll
        for (int dd = 0; dd < 4; dd++) {
            int d = dgrp * 16 + dd * 4;
            float4 v0 = *(const float4*)&vh[(size_t)(k0 + 2*cpr)     * DK + d];
            float4 v1 = *(const float4*)&vh[(size_t)(k0 + 2*cpr + 1) * DK + d];
            float a0[4] = {v0.x, v0.y, v0.z, v0.w};
            float a1[4] = {v1.x, v1.y, v1.z, v1.w};
            #pragma unroll
            for (int e = 0; e < 4; e++) {
                float h0 = __bfloat162float(__float2bfloat16_rn(a0[e]));
                float h1 = __bfloat162float(__float2bfloat16_rn(a1[e]));
                sVh[(d + e) * VST + cpr] = pack_bf16(h0, h1);
                sVl[(d + e) * VST + cpr] = pack_bf16(a0[e] - h0, a1[e] - h1);
            }
        }
        __syncthreads();

        float Sv[16][4];
        #pragma unroll
        for (int nt = 0; nt < 16; nt++)
            #pragma unroll
            for (int q = 0; q < 4; q++) Sv[nt][q] = 0.f;

        #pragma unroll
        for (int kc = 0; kc < 4; kc++) {
            int ao = abase + kc * 8;
            uint32_t ah[4], al[4];
            ah[0] = sQh[ao];              ah[1] = sQh[ao + 8*QST];
            ah[2] = sQh[ao + 4];          ah[3] = sQh[ao + 8*QST + 4];
            al[0] = sQl[ao];              al[1] = sQl[ao + 8*QST];
            al[2] = sQl[ao + 4];          al[3] = sQl[ao + 8*QST + 4];
            #pragma unroll
            for (int nt = 0; nt < 16; nt++) {
                int bo = (nt * 8 + r) * QST + kc * 8 + c4;
                uint32_t bh0 = sKh[bo], bh1 = sKh[bo + 4];
                uint32_t bl0 = sKl[bo], bl1 = sKl[bo + 4];
                mma_bf16(Sv[nt], ah, bh0, bh1);
                mma_bf16(Sv[nt], ah, bl0, bl1);
                mma_bf16(Sv[nt], al, bh0, bh1);
            }
        }

        if (kt == qt) {
            int row0 = wid * 16 + r;
            int row1 = row0 + 8;
            #pragma unroll
            for (int nt = 0; nt < 16; nt++) {
                int col = nt * 8 + c4 * 2;
                if (col     > row0) Sv[nt][0] = -1e30f;
                if (col + 1 > row0) Sv[nt][1] = -1e30f;
                if (col     > row1) Sv[nt][2] = -1e30f;
                if (col + 1 > row1) Sv[nt][3] = -1e30f;
            }
        }

        #pragma unroll
        for (int hrow = 0; hrow < 2; hrow++) {
            float tm = -CUDART_INF_F;
            #pragma unroll
            for (int nt = 0; nt < 16; nt++) {
                tm = fmaxf(tm, Sv[nt][2*hrow]);
                tm = fmaxf(tm, Sv[nt][2*hrow + 1]);
            }
            tm = fmaxf(tm, __shfl_xor_sync(0xffffffffu, tm, 1));
            tm = fmaxf(tm, __shfl_xor_sync(0xffffffffu, tm, 2));
            float mn = fmaxf(mrow[hrow], tm);
            float alpha = exp2a(mrow[hrow] - mn);
            float ps = 0.f;
            #pragma unroll
            for (int nt = 0; nt < 16; nt++) {
                float p0 = exp2a(Sv[nt][2*hrow]     - mn);
                float p1 = exp2a(Sv[nt][2*hrow + 1] - mn);
                Sv[nt][2*hrow]     = p0;
                Sv[nt][2*hrow + 1] = p1;
                ps += p0 + p1;
            }
            ps += __shfl_xor_sync(0xffffffffu, ps, 1);
            ps += __shfl_xor_sync(0xffffffffu, ps, 2);
            lrow[hrow] = lrow[hrow] * alpha + ps;
            mrow[hrow] = mn;
            #pragma unroll
            for (int nt2 = 0; nt2 < 8; nt2++) {
                O[nt2][2*hrow]     *= alpha;
                O[nt2][2*hrow + 1] *= alpha;
            }
        }

        #pragma unroll
        for (int nt = 0; nt < 16; nt++) {
            int w0 = (wid * 16 + r) * VST + nt * 4 + c4;
            float p0 = Sv[nt][0], p1 = Sv[nt][1];
            float h0 = __bfloat162float(__float2bfloat16_rn(p0));
            float h1 = __bfloat162float(__float2bfloat16_rn(p1));
            sPh[w0] = pack_bf16(h0, h1);
            sPl[w0] = pack_bf16(p0 - h0, p1 - h1);
            float p2 = Sv[nt][2], p3 = Sv[nt][3];
            float h2 = __bfloat162float(__float2bfloat16_rn(p2));
            float h3 = __bfloat162float(__float2bfloat16_rn(p3));
            sPh[w0 + 8*VST] = pack_bf16(h2, h3);
            sPl[w0 + 8*VST] = pack_bf16(p2 - h2, p3 - h3);
        }
        __syncwarp();

        #pragma unroll
        for (int kc2 = 0; kc2 < 8; kc2++) {
            int po = pbase + kc2 * 8;
            uint32_t ph[4], pl[4];
            ph[0] = sPh[po];              ph[1] = sPh[po + 8*VST];
            ph[2] = sPh[po + 4];          ph[3] = sPh[po + 8*VST + 4];
            pl[0] = sPl[po];              pl[1] = sPl[po + 8*VST];
            pl[2] = sPl[po + 4];          pl[3] = sPl[po + 8*VST + 4];
            #pragma unroll
            for (int nt2 = 0; nt2 < 8; nt2++) {
                int vo = (nt2 * 8 + r) * VST + kc2 * 8 + c4;
                uint32_t vh0 = sVh[vo], vh1 = sVh[vo + 4];
                uint32_t vl0 = sVl[vo], vl1 = sVl[vo + 4];
                mma_bf16(O[nt2], ph, vh0, vh1);
                mma_bf16(O[nt2], ph, vl0, vl1);
                mma_bf16(O[nt2], pl, vh0, vh1);
            }
        }
    }

    // ---- normalize + write hi/lo bf16 directly (feeds Wo GEMM) ----
    const int b = bh >> 4, h = bh & 15;
    const float inv0 = 1.0f / lrow[0];
    const float inv1 = 1.0f / lrow[1];
    const int row0g = q0 + wid * 16 + r;
    const int row1g = row0g + 8;
    #pragma unroll
    for (int nt2 = 0; nt2 < 8; nt2++) {
        int col = h * DK + nt2 * 8 + c4 * 2;
        float v00 = O[nt2][0] * inv0, v01 = O[nt2][1] * inv0;
        float v10 = O[nt2][2] * inv1, v11 = O[nt2][3] * inv1;
        float h00 = __bfloat162float(__float2bfloat16_rn(v00));
        float h01 = __bfloat162float(__float2bfloat16_rn(v01));
        float h10 = __bfloat162float(__float2bfloat16_rn(v10));
        float h11 = __bfloat162float(__float2bfloat16_rn(v11));
        size_t o0 = (size_t)(b * SS + row0g) * DD + col;
        size_t o1 = (size_t)(b * SS + row1g) * DD + col;
        *(uint32_t*)&ohi[o0] = pack_bf16(h00, h01);
        *(uint32_t*)&olo[o0] = pack_bf16(v00 - h00, v01 - h01);
        *(uint32_t*)&ohi[o1] = pack_bf16(h10, h11);
        *(uint32_t*)&olo[o1] = pack_bf16(v10 - h10, v11 - h11);
    }
}

// ---------------- launch --------------------------------------------------------
extern "C" void kernel_launch(void* const* d_in, const int* in_sizes, int n_in,
                              void* d_out, int out_size)
{
    (void)in_sizes; (void)n_in; (void)out_size;
    const float* x  = (const float*)d_in[0];
    const float* Wq = (const float*)d_in[1];
    const float* Wk = (const float*)d_in[2];
    const float* Wv = (const float*)d_in[3];
    const float* Wo = (const float*)d_in[4];
    const int*   tp = (const int*)d_in[5];
    float* out = (float*)d_out;

    float *qb, *kb, *vb, *ct, *st;
    __nv_bfloat16 *xhi, *xlo, *wqhi, *wqlo, *wkhi, *wklo, *wvhi, *wvlo, *wohi, *wolo, *abhi, *ablo;
    cudaGetSymbolAddress((void**)&qb, g_qbuf);
    cudaGetSymbolAddress((void**)&kb, g_kbuf);
    cudaGetSymbolAddress((void**)&vb, g_vbuf);
    cudaGetSymbolAddress((void**)&ct, g_ct);
    cudaGetSymbolAddress((void**)&st, g_st);
    cudaGetSymbolAddress((void**)&xhi, g_xhi);   cudaGetSymbolAddress((void**)&xlo, g_xlo);
    cudaGetSymbolAddress((void**)&wqhi, g_wqhi); cudaGetSymbolAddress((void**)&wqlo, g_wqlo);
    cudaGetSymbolAddress((void**)&wkhi, g_wkhi); cudaGetSymbolAddress((void**)&wklo, g_wklo);
    cudaGetSymbolAddress((void**)&wvhi, g_wvhi); cudaGetSymbolAddress((void**)&wvlo, g_wvlo);
    cudaGetSymbolAddress((void**)&wohi, g_wohi); cudaGetSymbolAddress((void**)&wolo, g_wolo);
    cudaGetSymbolAddress((void**)&abhi, g_abhi); cudaGetSymbolAddress((void**)&ablo, g_ablo);

    cudaFuncSetAttribute(gemm_mma2_kernel, cudaFuncAttributeMaxDynamicSharedMemorySize,
                         G2_SMEM_BYTES);
    cudaFuncSetAttribute(attn_mma_kernel, cudaFuncAttributeMaxDynamicSharedMemorySize,
                         ATTN_SMEM_BYTES);

    const int nx4 = BB*SS*DD/4, nw4 = DD*DD/4;
    cvt_hilo_kernel<<<(nx4 + 255)/256, 256>>>(x,  xhi,  xlo,  nx4);
    cvt_hilo_kernel<<<(nw4 + 255)/256, 256>>>(Wq, wqhi, wqlo, nw4);
    cvt_hilo_kernel<<<(nw4 + 255)/256, 256>>>(Wk, wkhi, wklo, nw4);
    cvt_hilo_kernel<<<(nw4 + 255)/256, 256>>>(Wv, wvhi, wvlo, nw4);
    cvt_hilo_kernel<<<(nw4 + 255)/256, 256>>>(Wo, wohi, wolo, nw4);
    rope_tab_kernel<<<(BB*SS*32 + 255)/256, 256>>>(tp, ct, st);

    dim3 gproj(DD / 128, (BB * SS) / 128);
    gemm_mma2_kernel<<<gproj, 256, G2_SMEM_BYTES>>>(xhi, xlo, wqhi, wqlo, ct, st, qb, 0);
    gemm_mma2_kernel<<<gproj, 256, G2_SMEM_BYTES>>>(xhi, xlo, wkhi, wklo, ct, st, kb, 0);
    gemm_mma2_kernel<<<gproj, 256, G2_SMEM_BYTES>>>(xhi, xlo, wvhi, wvlo, ct, st, vb, 1);

    attn_mma_kernel<<<dim3(SS / 128, BB * HH), 256, ATTN_SMEM_BYTES>>>(qb, kb, vb, abhi, ablo);

    gemm_mma2_kernel<<<gproj, 256, G2_SMEM_BYTES>>>(abhi, ablo, wohi, wolo, ct, st, out, 2);
}